// round 12
// baseline (speedup 1.0000x reference)
#include <cuda_runtime.h>
#include <cuda_fp16.h>
#include <cstdint>

#define BB   8
#define MM   4096
#define NN   16384
#define HH   128
#define WW   128
#define BN   (BB*NN)
#define TAUF 0.01f
#define EPSF 1e-8f
#define ITERS 100

#define NSTAGES 4096        // both phases: 4096 stages of 128 cols
#define MAXSLOTS 1024       // 2 segments x up to 512 CTAs

// smem: 3 slots x 36KB; slot = A[2 subtiles][16KB] + B[2 subtiles][2KB]
#define SLOT_A0   0
#define SLOT_A1   16384
#define SLOT_B0   32768
#define SLOT_B1   34816
#define SLOT_BYTES 36864
#define SM_TOTAL  (3 * SLOT_BYTES)     // 108 KB

// ---------------- device state (no allocations allowed) ----------------
__device__ __half g_Ah [(size_t)MM * NN];     // A fp16 row-major [i][j]
__device__ __half g_AhT[(size_t)MM * NN];     // A^T fp16 [j][i]
__device__ float  g_x[BN];
__device__ float  g_xbar[BN];
__device__ float  g_t[BN];
__device__ float  g_yb[2][2][BN];
__device__ __half g_t16[(size_t)16 * NN];     // rows 0-7 = hi(t), 8-15 = lo(t)*2048
__device__ __half g_r16[(size_t)16 * MM];     // rows 0-7 = hi(r), 8-15 = lo(r)*2048
__device__ float  g_rpart[(size_t)MAXSLOTS * 128 * 8];  // phase-1 partials [slot][rl][b]
__device__ float  g_gpart[(size_t)MAXSLOTS * 128 * 8];  // phase-2 partials [slot][rl][b]

// ---------------- helpers ----------------
#define SWZ(o) ((o) ^ (((o) >> 3) & 0x70))

#define CP16(DST, SRC) \
    asm volatile("cp.async.cg.shared.global [%0], [%1], 16;" :: "r"(DST), "l"(SRC))
#define CP_COMMIT() asm volatile("cp.async.commit_group;" ::: "memory")
#define CP_WAIT1()  asm volatile("cp.async.wait_group 1;"  ::: "memory")

#define LDM_X4(R0, R1, R2, R3, ADDR)                                          \
    asm volatile("ldmatrix.sync.aligned.m8n8.x4.shared.b16 {%0,%1,%2,%3}, [%4];" \
                 : "=r"(R0), "=r"(R1), "=r"(R2), "=r"(R3) : "r"(ADDR))

#define MMA16816(C, A0, A1, A2, A3, B0, B1)                                   \
    asm volatile("mma.sync.aligned.m16n8k16.row.col.f32.f16.f16.f32 "         \
                 "{%0,%1,%2,%3}, {%4,%5,%6,%7}, {%8,%9}, {%0,%1,%2,%3};"      \
                 : "+f"((C)[0]), "+f"((C)[1]), "+f"((C)[2]), "+f"((C)[3])     \
                 : "r"(A0), "r"(A1), "r"(A2), "r"(A3), "r"(B0), "r"(B1))

// ---------------- setup: A fp32 -> fp16 + fp16 transpose (one-time) ----------
__global__ void k_setup(const float* __restrict__ A) {
    __shared__ __half tile[32][33];
    int j0 = blockIdx.x * 32, i0 = blockIdx.y * 32;
    int tx = threadIdx.x, ty = threadIdx.y;          // (32, 8)
#pragma unroll
    for (int q = 0; q < 4; q++) {
        int il = ty + q * 8;
        float v = A[(size_t)(i0 + il) * NN + j0 + tx];
        __half h = __float2half_rn(v);
        g_Ah[(size_t)(i0 + il) * NN + j0 + tx] = h;
        tile[il][tx] = h;
    }
    __syncthreads();
#pragma unroll
    for (int q = 0; q < 4; q++) {
        int jl = ty + q * 8;
        g_AhT[(size_t)(j0 + jl) * MM + i0 + tx] = tile[tx][jl];
    }
}

// ---------------- zero init ----------------
__global__ void k_zero() {
    int idx = blockIdx.x * blockDim.x + threadIdx.x;
    if (idx < BN) {
        g_x[idx] = 0.f; g_xbar[idx] = 0.f;
        g_yb[0][0][idx] = 0.f; g_yb[0][1][idx] = 0.f;
    }
}

// ---------------- TV stencil + t16 hi/lo emit ----------------
__global__ void k_tv(int bi) {
    int idx = blockIdx.x * blockDim.x + threadIdx.x;
    if (idx >= BN) return;
    int p = idx & (NN - 1);
    int i = p >> 7;
    int j = p & 127;

    const float* yx = g_yb[bi][0];
    const float* yy = g_yb[bi][1];
    float*       oyx = g_yb[bi ^ 1][0];
    float*       oyy = g_yb[bi ^ 1][1];

    float yxv = yx[idx];
    float yyv = yy[idx];

    float dx = (j > 0) ? (yxv - yx[idx - 1])  : 0.f;
    float dy = (i > 0) ? (yyv - yy[idx - WW]) : 0.f;
    float t = g_x[idx] - TAUF * (dx + dy);
    g_t[idx] = t;

    __half hi = __float2half_rn(t);
    float  lo = (t - __half2float(hi)) * 2048.f;
    g_t16[idx] = hi;
    g_t16[(size_t)BN + idx] = __float2half_rn(lo);

    float xb = g_xbar[idx];
    float gx = (j < WW - 1) ? (xb - g_xbar[idx + 1])  : 0.f;
    float gy = (i < HH - 1) ? (xb - g_xbar[idx + WW]) : 0.f;

    float nyx = yxv + TAUF * gx;
    float nyy = yyv + TAUF * gy;
    float denom = fmaxf(fabsf(nyx), fabsf(nyy)) + EPSF;
    float inv = 1.f / denom;
    oyx[idx] = nyx * inv;
    oyy[idx] = nyy * inv;
}

// ---------------- unified HMMA GEMV kernel (static stage partition) ----------
// Global stage stream: stage gs in [0, 4096). Row-tile = gs >> tshift (128 rows),
// k-offset = (gs & tmask) * 128. CTA cta gets a contiguous range of q or q+1
// stages; flushes acc into slot 2*cta + seg at each row-tile boundary / end.
__global__ __launch_bounds__(128) void k_mma(int phase, int q, int rem) {
    extern __shared__ char sm[];
    unsigned smb = (unsigned)__cvta_generic_to_shared(sm);
    int tid = threadIdx.x, wid = tid >> 5, lane = tid & 31;
    int cta = blockIdx.x;

    const __half* Aop = phase ? g_AhT : g_Ah;
    const __half* Bop = phase ? g_r16 : g_t16;
    float*        outp = phase ? g_gpart : g_rpart;
    const int Ktot   = phase ? MM : NN;
    const int tshift = phase ? 5 : 7;
    const int tmask  = (1 << tshift) - 1;

    int thr   = rem * (q + 1);
    int start = (cta < rem) ? cta * (q + 1) : thr + (cta - rem) * q;
    int count = (cta < rem) ? q + 1 : q;
    int end   = start + count;

    // ---- stage fill: 2 sub-tiles, 18 x 16B cp.async per thread, one commit ----
    auto fill = [&](int gs, int slot) {
        unsigned slotb = smb + (unsigned)(slot * SLOT_BYTES);
        int tile = gs >> tshift;
        int koff = (gs & tmask) << 7;
        const __half* arow = Aop + ((size_t)tile << 7) * Ktot + koff;
        const __half* brow = Bop + koff;
#pragma unroll
        for (int half = 0; half < 2; half++) {
            const __half* asrc = arow + half * 64;
            unsigned abase = slotb + (half ? SLOT_A1 : SLOT_A0);
#pragma unroll
            for (int q8 = 0; q8 < 8; q8++) {
                int cc = tid + q8 * 128;              // row 0..127, c16 0..7
                int row = cc >> 3, c16 = cc & 7;
                unsigned off = (unsigned)(row * 128 + c16 * 16);
                CP16(abase + SWZ(off), asrc + (size_t)row * Ktot + c16 * 8);
            }
            const __half* bsrc = brow + half * 64;
            int br = tid >> 3, bc = tid & 7;          // row 0..15, c16 0..7
            unsigned boff = (unsigned)(br * 128 + bc * 16);
            CP16(slotb + (half ? SLOT_B1 : SLOT_B0) + SWZ(boff),
                 bsrc + (size_t)br * Ktot + bc * 8);
        }
        CP_COMMIT();
    };

    float acc[2][2][4];
#pragma unroll
    for (int mt = 0; mt < 2; mt++)
#pragma unroll
        for (int nt = 0; nt < 2; nt++)
#pragma unroll
            for (int z = 0; z < 4; z++) acc[mt][nt][z] = 0.f;

    fill(start, 0);
    fill(start + 1, 1);

    int l8 = lane & 7;
    int lq = lane >> 3;
    int gfold = lane >> 2, t4 = lane & 3;
    const float is = 1.f / 2048.f;

    int sl = 0;       // slot of compute stage
    int slf = 2;      // slot of fill stage (gs+2)
    int seg = 0;

    for (int gs = start; gs < end; gs++) {
        CP_WAIT1();
        __syncthreads();                 // stage gs visible; stage gs-1 consumed

        if (gs + 2 < end) { fill(gs + 2, slf); } else { CP_COMMIT(); }
        slf = (slf == 2) ? 0 : slf + 1;

        unsigned slotb = smb + (unsigned)(sl * SLOT_BYTES);
        sl = (sl == 2) ? 0 : sl + 1;

#pragma unroll
        for (int kk = 0; kk < 8; kk++) {
            unsigned abase = slotb + ((kk < 4) ? SLOT_A0 : SLOT_A1);
            unsigned bbase = slotb + ((kk < 4) ? SLOT_B0 : SLOT_B1);
            int k4 = kk & 3;

            unsigned brow = (lq >> 1) * 8 + l8;
            unsigned bcol = k4 * 32 + (lq & 1) * 16;
            unsigned b0, b1, b2, b3;
            LDM_X4(b0, b1, b2, b3, bbase + SWZ(brow * 128 + bcol));

#pragma unroll
            for (int mt = 0; mt < 2; mt++) {
                unsigned arow = wid * 32 + mt * 16 + (lq & 1) * 8 + l8;
                unsigned acol = k4 * 32 + (lq >> 1) * 16;
                unsigned a0, a1, a2, a3;
                LDM_X4(a0, a1, a2, a3, abase + SWZ(arow * 128 + acol));

                MMA16816(acc[mt][0], a0, a1, a2, a3, b0, b1);   // hi batches
                MMA16816(acc[mt][1], a0, a1, a2, a3, b2, b3);   // lo batches
            }
        }

        // flush at row-tile boundary or range end
        bool last = (gs + 1 == end) || (((gs + 1) >> tshift) != (gs >> tshift));
        if (last) {
            int slotid = 2 * cta + seg;
#pragma unroll
            for (int mt = 0; mt < 2; mt++) {
                int rl = wid * 32 + mt * 16 + gfold;
                float* d0 = outp + ((size_t)slotid * 128 + rl) * 8 + t4 * 2;
                float* d1 = outp + ((size_t)slotid * 128 + rl + 8) * 8 + t4 * 2;
                *reinterpret_cast<float2*>(d0) = make_float2(
                    acc[mt][0][0] + acc[mt][1][0] * is,
                    acc[mt][0][1] + acc[mt][1][1] * is);
                *reinterpret_cast<float2*>(d1) = make_float2(
                    acc[mt][0][2] + acc[mt][1][2] * is,
                    acc[mt][0][3] + acc[mt][1][3] * is);
            }
#pragma unroll
            for (int mt = 0; mt < 2; mt++)
#pragma unroll
                for (int nt = 0; nt < 2; nt++)
#pragma unroll
                    for (int z = 0; z < 4; z++) acc[mt][nt][z] = 0.f;
            seg++;
        }
    }
}

// ---------------- r prep: r = sum(rpart segs) - meas -> hi/lo fp16 -----------
__global__ void k_rprep(const float* __restrict__ meas, int q, int rem) {
    int idx = blockIdx.x * blockDim.x + threadIdx.x;   // 32768
    int i = idx >> 3, b = idx & 7;
    int tile = i >> 7, rl = i & 127;
    int gsa = tile << 7;                 // phase0: 128 stages per row-tile
    int thr = rem * (q + 1);

    int c0 = (gsa < thr) ? gsa / (q + 1) : rem + (gsa - thr) / q;
    int gsb = gsa + 127;
    int c1 = (gsb < thr) ? gsb / (q + 1) : rem + (gsb - thr) / q;

    float v = -meas[b * MM + i];
    for (int cc = c0; cc <= c1; cc++) {
        int st = (cc < rem) ? cc * (q + 1) : thr + (cc - rem) * q;
        int slot = 2 * cc + (st < gsa ? 1 : 0);
        v += g_rpart[((size_t)slot * 128 + rl) * 8 + b];
    }
    __half hi = __float2half_rn(v);
    float  lo = (v - __half2float(hi)) * 2048.f;
    g_r16[(size_t)b * MM + i] = hi;
    g_r16[(size_t)(b + 8) * MM + i] = __float2half_rn(lo);
}

// ---------------- finish: x = t - grad ; xbar = 2x - xbar_old ----------------
__global__ void k_fin(int q, int rem) {
    int idx = blockIdx.x * blockDim.x + threadIdx.x;
    if (idx >= BN) return;
    int b = idx >> 14;
    int j = idx & (NN - 1);
    int tile = j >> 7, rl = j & 127;
    int gsa = tile << 5;                 // phase1: 32 stages per row-tile
    int thr = rem * (q + 1);

    int c0 = (gsa < thr) ? gsa / (q + 1) : rem + (gsa - thr) / q;
    int gsb = gsa + 31;
    int c1 = (gsb < thr) ? gsb / (q + 1) : rem + (gsb - thr) / q;

    float s = 0.f;
    for (int cc = c0; cc <= c1; cc++) {
        int st = (cc < rem) ? cc * (q + 1) : thr + (cc - rem) * q;
        int slot = 2 * cc + (st < gsa ? 1 : 0);
        s += g_gpart[((size_t)slot * 128 + rl) * 8 + b];
    }
    float xn = g_t[idx] - s;
    float xbo = g_xbar[idx];
    g_x[idx] = xn;
    g_xbar[idx] = 2.f * xn - xbo;
}

// ---------------- output copy ----------------
__global__ void k_copy(float* __restrict__ out) {
    int idx = blockIdx.x * blockDim.x + threadIdx.x;
    if (idx < BN) out[idx] = g_x[idx];
}

// ---------------- launch ----------------
extern "C" void kernel_launch(void* const* d_in, const int* in_sizes, int n_in,
                              void* d_out, int out_size) {
    const float* meas = (const float*)d_in[0];
    const float* A    = (const float*)d_in[1];
    if (n_in >= 2 && in_sizes[0] != BB * MM) {
        meas = (const float*)d_in[1];
        A    = (const float*)d_in[0];
    }
    float* out = (float*)d_out;

    int nsm = 148;
    cudaDeviceGetAttribute(&nsm, cudaDevAttrMultiProcessorCount, 0);
    int ncta = 2 * nsm;
    if (ncta > MAXSLOTS / 2) ncta = MAXSLOTS / 2;
    int q   = NSTAGES / ncta;
    int rem = NSTAGES % ncta;

    cudaFuncSetAttribute(k_mma, cudaFuncAttributeMaxDynamicSharedMemorySize, SM_TOTAL);

    k_setup<<<dim3(NN / 32, MM / 32), dim3(32, 8)>>>(A);
    k_zero<<<BN / 256, 256>>>();

    for (int it = 0; it < ITERS; it++) {
        int bi = it & 1;
        k_tv<<<BN / 256, 256>>>(bi);
        k_mma<<<ncta, 128, SM_TOTAL>>>(0, q, rem);
        k_rprep<<<(MM * 8) / 256, 256>>>(meas, q, rem);
        k_mma<<<ncta, 128, SM_TOTAL>>>(1, q, rem);
        k_fin<<<BN / 256, 256>>>(q, rem);
    }
    k_copy<<<BN / 256, 256>>>(out);
}